// round 5
// baseline (speedup 1.0000x reference)
#include <cuda_runtime.h>
#include <cstdint>

#define NMAX 100000
#define EMAX 1600000
#define CDIV(a,b) (((a)+(b)-1)/(b))

// ---------------- scratch (static device globals; no runtime alloc) ----------------
__device__ float g_bufA[NMAX*128];   // node features (layer input / agg output)
__device__ float g_bufB[NMAX*128];   // GEMM output (pre-aggregation)
__device__ int   g_cnt[NMAX];
__device__ int   g_rowptr[NMAX+1];
__device__ int   g_cols[EMAX];
__device__ float g_vals[EMAX];
__device__ float g_dis[NMAX];        // rsqrt(deg)
__device__ float g_invdeg[NMAX];     // 1/deg  (self-loop norm)
__device__ float g_stats[256];       // [0:128) sum, [128:256) sumsq
__device__ float g_scale[128];
__device__ float g_shift[128];
__device__ int   g_is64;
// bf16-split weights, fragment-ordered for mma.m16n8k16: [k16][ntile][lane][2regs]
__device__ __align__(16) unsigned g_wfh[8192];
__device__ __align__(16) unsigned g_wfl[8192];

// ---------------- bf16 helpers ----------------
__device__ __forceinline__ unsigned pack_bf16(float lo, float hi){
    unsigned r; asm("cvt.rn.bf16x2.f32 %0, %1, %2;" : "=r"(r) : "f"(hi), "f"(lo)); return r;
}
__device__ __forceinline__ float bf_lo(unsigned p){ return __uint_as_float(p << 16); }
__device__ __forceinline__ float bf_hi(unsigned p){ return __uint_as_float(p & 0xFFFF0000u); }

__device__ __forceinline__ void mma_bf16(float* d, const unsigned* a, const unsigned* b){
    asm volatile("mma.sync.aligned.m16n8k16.row.col.f32.bf16.bf16.f32 "
        "{%0,%1,%2,%3}, {%4,%5,%6,%7}, {%8,%9}, {%0,%1,%2,%3};"
        : "+f"(d[0]),"+f"(d[1]),"+f"(d[2]),"+f"(d[3])
        : "r"(a[0]),"r"(a[1]),"r"(a[2]),"r"(a[3]), "r"(b[0]),"r"(b[1]));
}

// ---------------- edge index access (int64 vs int32, detected on device) -----------
__device__ __forceinline__ long long edge_at(const void* ei, long long idx, int is64){
    return is64 ? ((const long long*)ei)[idx] : (long long)((const int*)ei)[idx];
}

__global__ void k_detect(const void* ei){
    if (blockIdx.x==0 && threadIdx.x==0){
        const int* p = (const int*)ei;
        int all0 = 1;
        for (int k=0;k<128;k++) if (p[2*k+1]!=0){ all0=0; break; }
        g_is64 = all0;   // node ids < 2^31 -> high words all zero iff int64
    }
}

// ---------------- degree / CSR build ----------------
__global__ void k_zero_cnt(int n){
    int i = blockIdx.x*blockDim.x + threadIdx.x;
    if (i < n) g_cnt[i] = 0;
}

__global__ void k_hist(const void* ei, int E){
    int e = blockIdx.x*blockDim.x + threadIdx.x;
    if (e >= E) return;
    int is64 = g_is64;
    int d = (int)edge_at(ei, (long long)E + e, is64);
    atomicAdd(&g_cnt[d], 1);
}

__global__ void k_deg(int n){
    int i = blockIdx.x*blockDim.x + threadIdx.x;
    if (i >= n) return;
    float c = (float)(g_cnt[i] + 1);     // +1 self loop
    g_dis[i]    = rsqrtf(c);
    g_invdeg[i] = 1.0f / c;
}

// single-block exclusive scan of g_cnt -> g_rowptr (n up to 100k); also zero stats
__global__ void k_scan(int n){
    __shared__ int sums[1024];
    int tid = threadIdx.x;
    if (tid < 256) g_stats[tid] = 0.f;
    int chunk = (n + 1023) / 1024;
    int start = tid * chunk;
    int end   = min(start + chunk, n);
    int s = 0;
    for (int i = start; i < end; i++) s += g_cnt[i];
    sums[tid] = s;
    __syncthreads();
    for (int off = 1; off < 1024; off <<= 1){
        int v = (tid >= off) ? sums[tid - off] : 0;
        __syncthreads();
        sums[tid] += v;
        __syncthreads();
    }
    int excl = (tid == 0) ? 0 : sums[tid-1];
    int off = excl;
    for (int i = start; i < end; i++){ g_rowptr[i] = off; off += g_cnt[i]; }
    if (tid == 1023) g_rowptr[n] = sums[1023];
}

__global__ void k_fill(const void* ei, int E){
    int e = blockIdx.x*blockDim.x + threadIdx.x;
    if (e >= E) return;
    int is64 = g_is64;
    int s = (int)edge_at(ei, e, is64);
    int d = (int)edge_at(ei, (long long)E + e, is64);
    int pos = g_rowptr[d] + atomicAdd(&g_cnt[d], 1);
    g_cols[pos] = s;
    g_vals[pos] = g_dis[s] * g_dis[d];
}

// ---------------- weight split into fragment-ordered bf16 hi/lo ----------------
// W is [128][DOUT] row-major. Fragments for mma.m16n8k16.row.col:
// b0 = W[k16*16 + 2t + {0,1}][n],  b1 = W[k16*16 + 2t + 8 + {0,1}][n],  lane = (n&7)*4 + t
template<int DOUT>
__global__ void k_wsplit(const float* __restrict__ W){
    constexpr int NT = DOUT/8;
    int idx = blockIdx.x*blockDim.x + threadIdx.x;   // over k-pairs x n
    if (idx >= 64*DOUT) return;
    int kp = idx / DOUT;          // 0..63 (even k / 2)
    int nn = idx % DOUT;
    int k  = kp*2;
    float f0 = W[(size_t)k*DOUT + nn];
    float f1 = W[(size_t)(k+1)*DOUT + nn];
    unsigned h = pack_bf16(f0, f1);
    unsigned l = pack_bf16(f0 - bf_lo(h), f1 - bf_hi(h));
    int kk  = k & 15;
    int reg = kk >> 3;            // b0 / b1
    int t   = (kk >> 1) & 3;
    int k16 = k >> 4;
    int g   = nn & 7, nt = nn >> 3;
    int pos = (((k16*NT + nt)*32) + g*4 + t)*2 + reg;
    g_wfh[pos] = h;
    g_wfl[pos] = l;
}

// ---------------- GEMM: C(n x DOUT) = relu(bn(A)) @ W via bf16x3 mma.sync ----------
// Block 256 thr = 8 warps (4m x 2n); block tile 128 x DOUT; warp tile 32 x DOUT/2.
// D += Ahi*Whi + Ahi*Wlo + Alo*Whi  (fp32 accum; dropped lo*lo ~ 2^-18)
template<int DOUT, int ASEL>
__global__ void __launch_bounds__(256) k_gemm_bf(const float* __restrict__ Aext, int n){
    constexpr int NT  = DOUT/8;
    constexpr int NTW = NT/2;                 // n-tiles per warp (8 or 4)
    constexpr int LDA = 40;
    __shared__ __align__(16) float As[128*LDA];

    const float* A = (ASEL==0) ? Aext : g_bufA;
    int tid = threadIdx.x, lane = tid & 31, warp = tid >> 5;
    int wm = warp >> 1, wn = warp & 1;
    int g = lane >> 2, t = lane & 3;
    int rowBase = blockIdx.x * 128;

    float acc[2][NTW][4];
    #pragma unroll
    for (int a=0;a<2;a++)
        #pragma unroll
        for (int b=0;b<NTW;b++)
            #pragma unroll
            for (int c=0;c<4;c++) acc[a][b][c] = 0.f;

    const uint2* WH = (const uint2*)g_wfh;
    const uint2* WL = (const uint2*)g_wfl;

    for (int kt = 0; kt < 128; kt += 32){
        // ---- A tile load (fused BN+ReLU when ASEL==1) ----
        #pragma unroll
        for (int i=0;i<4;i++){
            int idx  = tid + i*256;           // 0..1023
            int r    = idx >> 3;              // 0..127
            int c4   = idx & 7;               // float4 within 32 cols
            int grow = rowBase + r;
            float4 v = make_float4(0.f,0.f,0.f,0.f);
            if (grow < n) v = *(const float4*)&A[(size_t)grow*128 + kt + c4*4];
            if (ASEL == 1){
                float4 sc = *(const float4*)&g_scale[kt + c4*4];
                float4 sh = *(const float4*)&g_shift[kt + c4*4];
                v.x = fmaxf(fmaf(v.x, sc.x, sh.x), 0.f);
                v.y = fmaxf(fmaf(v.y, sc.y, sh.y), 0.f);
                v.z = fmaxf(fmaf(v.z, sc.z, sh.z), 0.f);
                v.w = fmaxf(fmaf(v.w, sc.w, sh.w), 0.f);
            }
            *(float4*)&As[r*LDA + c4*4] = v;
        }
        __syncthreads();

        #pragma unroll
        for (int kk = 0; kk < 32; kk += 16){
            int k16idx = (kt + kk) >> 4;
            // A fragments (2 m-tiles): bf16 hi/lo split from smem
            unsigned ah[2][4], al[2][4];
            #pragma unroll
            for (int mt=0; mt<2; mt++){
                int r0 = wm*32 + mt*16;
                #pragma unroll
                for (int q=0; q<4; q++){
                    int rr = r0 + g + (q & 1)*8;
                    int cc = kk + 2*t + (q >> 1)*8;
                    float2 f = *(const float2*)&As[rr*LDA + cc];
                    unsigned h = pack_bf16(f.x, f.y);
                    ah[mt][q] = h;
                    al[mt][q] = pack_bf16(f.x - bf_lo(h), f.y - bf_hi(h));
                }
            }
            #pragma unroll
            for (int nt=0; nt<NTW; nt++){
                int off = (k16idx*NT + wn*NTW + nt)*32 + lane;
                uint2 bh = __ldg(&WH[off]);
                uint2 bl = __ldg(&WL[off]);
                unsigned bhv[2] = {bh.x, bh.y};
                unsigned blv[2] = {bl.x, bl.y};
                #pragma unroll
                for (int mt=0; mt<2; mt++){
                    mma_bf16(acc[mt][nt], ah[mt], bhv);
                    mma_bf16(acc[mt][nt], ah[mt], blv);
                    mma_bf16(acc[mt][nt], al[mt], bhv);
                }
            }
        }
        __syncthreads();
    }

    // ---- store C -> g_bufB ----
    #pragma unroll
    for (int mt=0; mt<2; mt++){
        #pragma unroll
        for (int nt=0; nt<NTW; nt++){
            int col = (wn*NTW + nt)*8 + t*2;
            int r0  = rowBase + wm*32 + mt*16 + g;
            if (r0 < n)
                *(float2*)&g_bufB[(size_t)r0*DOUT + col] =
                    make_float2(acc[mt][nt][0], acc[mt][nt][1]);
            if (r0 + 8 < n)
                *(float2*)&g_bufB[(size_t)(r0+8)*DOUT + col] =
                    make_float2(acc[mt][nt][2], acc[mt][nt][3]);
        }
    }
}

// ---------------- aggregation + fused BN statistics ----------------
template<int D>
__global__ void __launch_bounds__(256) k_agg(int n){
    constexpr int F   = D/4;
    constexpr int NPW = 32/F;
    __shared__ float ss[128], sq[128];
    int tid = threadIdx.x;
    if (tid < D){ ss[tid] = 0.f; sq[tid] = 0.f; }
    __syncthreads();

    int lane  = tid & 31;
    int warp0 = (blockIdx.x*blockDim.x + tid) >> 5;
    int nwarp = (gridDim.x*blockDim.x) >> 5;
    int fi  = lane % F;
    int sub = lane / F;

    const float4* t = (const float4*)g_bufB;
    float4* o = (float4*)g_bufA;

    float lsum[4] = {0,0,0,0}, lsq[4] = {0,0,0,0};

    for (int node = warp0*NPW + sub; node < n; node += nwarp*NPW){
        float idg = g_invdeg[node];
        float4 v = t[(size_t)node*F + fi];
        float4 acc = make_float4(v.x*idg, v.y*idg, v.z*idg, v.w*idg);

        int p0 = g_rowptr[node], p1 = g_rowptr[node+1];
        int p = p0;
        for (; p + 1 < p1; p += 2){
            int   s0 = g_cols[p],   s1 = g_cols[p+1];
            float w0 = g_vals[p],   w1 = g_vals[p+1];
            float4 u0 = t[(size_t)s0*F + fi];
            float4 u1 = t[(size_t)s1*F + fi];
            acc.x = fmaf(w0,u0.x, fmaf(w1,u1.x, acc.x));
            acc.y = fmaf(w0,u0.y, fmaf(w1,u1.y, acc.y));
            acc.z = fmaf(w0,u0.z, fmaf(w1,u1.z, acc.z));
            acc.w = fmaf(w0,u0.w, fmaf(w1,u1.w, acc.w));
        }
        if (p < p1){
            int   s0 = g_cols[p];
            float w0 = g_vals[p];
            float4 u0 = t[(size_t)s0*F + fi];
            acc.x = fmaf(w0,u0.x, acc.x);
            acc.y = fmaf(w0,u0.y, acc.y);
            acc.z = fmaf(w0,u0.z, acc.z);
            acc.w = fmaf(w0,u0.w, acc.w);
        }
        o[(size_t)node*F + fi] = acc;

        lsum[0] += acc.x; lsq[0] += acc.x*acc.x;
        lsum[1] += acc.y; lsq[1] += acc.y*acc.y;
        lsum[2] += acc.z; lsq[2] += acc.z*acc.z;
        lsum[3] += acc.w; lsq[3] += acc.w*acc.w;
    }

    int ch = fi*4;
    atomicAdd(&ss[ch+0], lsum[0]); atomicAdd(&sq[ch+0], lsq[0]);
    atomicAdd(&ss[ch+1], lsum[1]); atomicAdd(&sq[ch+1], lsq[1]);
    atomicAdd(&ss[ch+2], lsum[2]); atomicAdd(&sq[ch+2], lsq[2]);
    atomicAdd(&ss[ch+3], lsum[3]); atomicAdd(&sq[ch+3], lsq[3]);
    __syncthreads();
    if (tid < D){
        atomicAdd(&g_stats[tid],       ss[tid]);
        atomicAdd(&g_stats[128 + tid], sq[tid]);
    }
}

// ---------------- batch-norm finalize ----------------
__global__ void k_bn_final(const float* __restrict__ g, const float* __restrict__ be,
                           int n, int D){
    int c = threadIdx.x;                 // 256 threads
    float sc = 0.f, sh = 0.f;
    if (c < D){
        float inv_n = 1.0f / (float)n;
        float mu  = g_stats[c] * inv_n;
        float var = g_stats[128 + c] * inv_n - mu*mu;
        sc = g[c] * rsqrtf(var + 1e-5f);
        sh = be[c] - mu*sc;
    }
    __syncthreads();
    g_stats[c] = 0.f;
    if (c < D){ g_scale[c] = sc; g_shift[c] = sh; }
}

// ---------------- head ----------------
__global__ void __launch_bounds__(256) k_head(const float* __restrict__ wc1,
                                              const float* __restrict__ bc1,
                                              const float* __restrict__ wc2,
                                              const float* __restrict__ bc2,
                                              float* __restrict__ out, int n){
    __shared__ float w1s[64*32];
    __shared__ float b1s[32], w2s[32], scs[64], shs[64];
    int tid = threadIdx.x;
    for (int i = tid; i < 64*32; i += 256) w1s[i] = wc1[i];
    if (tid < 32){ b1s[tid] = bc1[tid]; w2s[tid] = wc2[tid]; }
    if (tid < 64){ scs[tid] = g_scale[tid]; shs[tid] = g_shift[tid]; }
    __syncthreads();

    int warp = (blockIdx.x*256 + tid) >> 5;
    int lane = tid & 31;
    if (warp >= n) return;

    const float* row = &g_bufA[(size_t)warp * 64];
    float a0 = b1s[lane], a1 = 0.f, a2 = 0.f, a3 = 0.f;
    #pragma unroll
    for (int k = 0; k < 64; k += 4){
        float v0 = fmaxf(fmaf(row[k+0], scs[k+0], shs[k+0]), 0.f);
        float v1 = fmaxf(fmaf(row[k+1], scs[k+1], shs[k+1]), 0.f);
        float v2 = fmaxf(fmaf(row[k+2], scs[k+2], shs[k+2]), 0.f);
        float v3 = fmaxf(fmaf(row[k+3], scs[k+3], shs[k+3]), 0.f);
        a0 = fmaf(v0, w1s[(k+0)*32 + lane], a0);
        a1 = fmaf(v1, w1s[(k+1)*32 + lane], a1);
        a2 = fmaf(v2, w1s[(k+2)*32 + lane], a2);
        a3 = fmaf(v3, w1s[(k+3)*32 + lane], a3);
    }
    float h = fmaxf((a0+a1)+(a2+a3), 0.f) * w2s[lane];
    #pragma unroll
    for (int off = 16; off; off >>= 1) h += __shfl_xor_sync(0xffffffff, h, off);
    if (lane == 0) out[warp] = h + bc2[0];
}

// ---------------- launch ----------------
extern "C" void kernel_launch(void* const* d_in, const int* in_sizes, int n_in,
                              void* d_out, int out_size){
    const float* x   = (const float*)d_in[0];
    const void*  ei  = d_in[1];
    const float* w0  = (const float*)d_in[2];
    const float* g0  = (const float*)d_in[4];
    const float* be0 = (const float*)d_in[5];
    const float* w1  = (const float*)d_in[6];
    const float* g1  = (const float*)d_in[8];
    const float* be1 = (const float*)d_in[9];
    const float* w2  = (const float*)d_in[10];
    const float* g2  = (const float*)d_in[12];
    const float* be2 = (const float*)d_in[13];
    const float* wc1 = (const float*)d_in[14];
    const float* bc1 = (const float*)d_in[15];
    const float* wc2 = (const float*)d_in[16];
    const float* bc2 = (const float*)d_in[17];
    float* out = (float*)d_out;

    int n = in_sizes[0] / 128;
    int E = in_sizes[1] / 2;

    const int AGG_GRID = 1184;           // 148 SMs x 8
    int gemmGrid = CDIV(n, 128);

    // my launch #4 = layer-0 GEMM (harness launches 2 kernels first; ncu -s 5 -c 1)
    k_detect<<<1,1>>>(ei);                                       // 1
    k_zero_cnt<<<CDIV(n,256),256>>>(n);                          // 2
    k_wsplit<128><<<CDIV(64*128,256),256>>>(w0);                 // 3
    k_gemm_bf<128,0><<<gemmGrid,256>>>(x, n);                    // 4 <- profiled
    k_hist<<<CDIV(E,256),256>>>(ei, E);                          // 5
    k_deg<<<CDIV(n,256),256>>>(n);                               // 6
    k_scan<<<1,1024>>>(n);                                       // 7 (also zeroes stats)
    k_zero_cnt<<<CDIV(n,256),256>>>(n);                          // 8
    k_fill<<<CDIV(E,256),256>>>(ei, E);                          // 9

    // ---- layer 0 (128 -> 128) ----
    k_agg<128><<<AGG_GRID,256>>>(n);                             // 10
    k_bn_final<<<1,256>>>(g0, be0, n, 128);                      // 11

    // ---- layer 1 (128 -> 128) ----
    k_wsplit<128><<<CDIV(64*128,256),256>>>(w1);                 // 12
    k_gemm_bf<128,1><<<gemmGrid,256>>>(nullptr, n);              // 13
    k_agg<128><<<AGG_GRID,256>>>(n);                             // 14
    k_bn_final<<<1,256>>>(g1, be1, n, 128);                      // 15

    // ---- layer 2 (128 -> 64) ----
    k_wsplit<64><<<CDIV(64*64,256),256>>>(w2);                   // 16
    k_gemm_bf<64,1><<<gemmGrid,256>>>(nullptr, n);               // 17
    k_agg<64><<<AGG_GRID,256>>>(n);                              // 18
    k_bn_final<<<1,256>>>(g2, be2, n, 64);                       // 19

    // ---- head ----
    k_head<<<CDIV(n*32,256),256>>>(wc1, bc1, wc2, bc2, out, n);  // 20
}

// round 6
// speedup vs baseline: 1.3576x; 1.3576x over previous
#include <cuda_runtime.h>
#include <cstdint>

#define NMAX 100000
#define EMAX 1600000
#define CDIV(a,b) (((a)+(b)-1)/(b))

// ---------------- scratch (static device globals; no runtime alloc) ----------------
__device__ float g_bufA[NMAX*128];   // node features (layer input / agg output)
__device__ float g_bufB[NMAX*128];   // GEMM output (pre-aggregation)
__device__ int   g_cnt[NMAX];
__device__ int   g_rowptr[NMAX+1];
__device__ int   g_cols[EMAX];
__device__ float g_vals[EMAX];
__device__ float g_dis[NMAX];        // rsqrt(deg)
__device__ float g_invdeg[NMAX];     // 1/deg  (self-loop norm)
__device__ float g_stats[256];       // [0:128) sum, [128:256) sumsq
__device__ float g_scale[128];
__device__ float g_shift[128];
__device__ int   g_is64;
// bf16-split weights, fragment-ordered for mma.m16n8k16: [k16][ntile][lane][2regs]
__device__ __align__(16) unsigned g_wfh[8192];
__device__ __align__(16) unsigned g_wfl[8192];

// ---------------- bf16 helpers ----------------
__device__ __forceinline__ unsigned pack_bf16(float lo, float hi){
    unsigned r; asm("cvt.rn.bf16x2.f32 %0, %1, %2;" : "=r"(r) : "f"(hi), "f"(lo)); return r;
}
__device__ __forceinline__ float bf_lo(unsigned p){ return __uint_as_float(p << 16); }
__device__ __forceinline__ float bf_hi(unsigned p){ return __uint_as_float(p & 0xFFFF0000u); }

__device__ __forceinline__ void mma_bf16(float* d, const unsigned* a, const unsigned* b){
    asm volatile("mma.sync.aligned.m16n8k16.row.col.f32.bf16.bf16.f32 "
        "{%0,%1,%2,%3}, {%4,%5,%6,%7}, {%8,%9}, {%0,%1,%2,%3};"
        : "+f"(d[0]),"+f"(d[1]),"+f"(d[2]),"+f"(d[3])
        : "r"(a[0]),"r"(a[1]),"r"(a[2]),"r"(a[3]), "r"(b[0]),"r"(b[1]));
}

// ---------------- edge index access (int64 vs int32, detected on device) -----------
__device__ __forceinline__ long long edge_at(const void* ei, long long idx, int is64){
    return is64 ? ((const long long*)ei)[idx] : (long long)((const int*)ei)[idx];
}

__global__ void k_detect(const void* ei){
    if (blockIdx.x==0 && threadIdx.x==0){
        const int* p = (const int*)ei;
        int all0 = 1;
        for (int k=0;k<128;k++) if (p[2*k+1]!=0){ all0=0; break; }
        g_is64 = all0;   // node ids < 2^31 -> high words all zero iff int64
    }
}

// ---------------- degree / CSR build ----------------
__global__ void k_zero_cnt(int n){
    int i = blockIdx.x*blockDim.x + threadIdx.x;
    if (i < n) g_cnt[i] = 0;
}

__global__ void k_hist(const void* ei, int E){
    int e = blockIdx.x*blockDim.x + threadIdx.x;
    if (e >= E) return;
    int is64 = g_is64;
    int d = (int)edge_at(ei, (long long)E + e, is64);
    atomicAdd(&g_cnt[d], 1);
}

__global__ void k_deg(int n){
    int i = blockIdx.x*blockDim.x + threadIdx.x;
    if (i >= n) return;
    float c = (float)(g_cnt[i] + 1);     // +1 self loop
    g_dis[i]    = rsqrtf(c);
    g_invdeg[i] = 1.0f / c;
}

// single-block exclusive scan of g_cnt -> g_rowptr (n up to 100k); also zero stats
__global__ void k_scan(int n){
    __shared__ int sums[1024];
    int tid = threadIdx.x;
    if (tid < 256) g_stats[tid] = 0.f;
    int chunk = (n + 1023) / 1024;
    int start = tid * chunk;
    int end   = min(start + chunk, n);
    int s = 0;
    for (int i = start; i < end; i++) s += g_cnt[i];
    sums[tid] = s;
    __syncthreads();
    for (int off = 1; off < 1024; off <<= 1){
        int v = (tid >= off) ? sums[tid - off] : 0;
        __syncthreads();
        sums[tid] += v;
        __syncthreads();
    }
    int excl = (tid == 0) ? 0 : sums[tid-1];
    int off = excl;
    for (int i = start; i < end; i++){ g_rowptr[i] = off; off += g_cnt[i]; }
    if (tid == 1023) g_rowptr[n] = sums[1023];
}

__global__ void k_fill(const void* ei, int E){
    int e = blockIdx.x*blockDim.x + threadIdx.x;
    if (e >= E) return;
    int is64 = g_is64;
    int s = (int)edge_at(ei, e, is64);
    int d = (int)edge_at(ei, (long long)E + e, is64);
    int pos = g_rowptr[d] + atomicAdd(&g_cnt[d], 1);
    g_cols[pos] = s;
    g_vals[pos] = g_dis[s] * g_dis[d];
}

// ---------------- weight split into fragment-ordered bf16 hi/lo ----------------
// W is [128][DOUT] row-major. Fragments for mma.m16n8k16.row.col:
// b0 = W[k16*16 + 2t + {0,1}][n],  b1 = W[k16*16 + 2t + 8 + {0,1}][n],  lane = (n&7)*4 + t
template<int DOUT>
__global__ void k_wsplit(const float* __restrict__ W){
    constexpr int NT = DOUT/8;
    int idx = blockIdx.x*blockDim.x + threadIdx.x;   // over k-pairs x n
    if (idx >= 64*DOUT) return;
    int kp = idx / DOUT;          // 0..63 (even k / 2)
    int nn = idx % DOUT;
    int k  = kp*2;
    float f0 = W[(size_t)k*DOUT + nn];
    float f1 = W[(size_t)(k+1)*DOUT + nn];
    unsigned h = pack_bf16(f0, f1);
    unsigned l = pack_bf16(f0 - bf_lo(h), f1 - bf_hi(h));
    int kk  = k & 15;
    int reg = kk >> 3;            // b0 / b1
    int t   = (kk >> 1) & 3;
    int k16 = k >> 4;
    int g   = nn & 7, nt = nn >> 3;
    int pos = (((k16*NT + nt)*32) + g*4 + t)*2 + reg;
    g_wfh[pos] = h;
    g_wfl[pos] = l;
}

// ---------------- GEMM: C(n x DOUT) = relu(bn(A)) @ W via bf16x3 mma.sync ----------
// Whole-K A tile (128x128 fp32, 69.6KB dynamic smem, LDA=136 conflict-free), loaded
// once with MLP=16, ONE sync, then 384 MMAs sync-free. 2 CTAs/SM (<=128 regs).
// D += Ahi*Whi + Ahi*Wlo + Alo*Whi  (fp32 accum; dropped lo*lo ~ 2^-18)
template<int DOUT, int ASEL>
__global__ void __launch_bounds__(256, 2) k_gemm_bf(const float* __restrict__ Aext, int n){
    constexpr int NT  = DOUT/8;
    constexpr int NTW = NT/2;                 // n-tiles per warp (8 or 4)
    constexpr int LDA = 136;                  // stride mod 32 = 8 -> conflict-free
    extern __shared__ float As[];             // 128*136*4 = 69632 B

    const float* A = (ASEL==0) ? Aext : g_bufA;
    int tid = threadIdx.x, lane = tid & 31, warp = tid >> 5;
    int wm = warp >> 1, wn = warp & 1;
    int g = lane >> 2, t = lane & 3;
    int rowBase = blockIdx.x * 128;

    float acc[2][NTW][4];
    #pragma unroll
    for (int a=0;a<2;a++)
        #pragma unroll
        for (int b=0;b<NTW;b++)
            #pragma unroll
            for (int c=0;c<4;c++) acc[a][b][c] = 0.f;

    // ---- full A tile load: 128 rows x 128 cols, fused BN+ReLU when ASEL==1 ----
    #pragma unroll
    for (int i=0;i<16;i++){
        int idx  = tid + i*256;           // 0..4095
        int r    = idx >> 5;              // 0..127
        int c4   = idx & 31;              // float4 within 128 cols
        int grow = rowBase + r;
        float4 v = make_float4(0.f,0.f,0.f,0.f);
        if (grow < n) v = *(const float4*)&A[(size_t)grow*128 + c4*4];
        if (ASEL == 1){
            float4 sc = *(const float4*)&g_scale[c4*4];
            float4 sh = *(const float4*)&g_shift[c4*4];
            v.x = fmaxf(fmaf(v.x, sc.x, sh.x), 0.f);
            v.y = fmaxf(fmaf(v.y, sc.y, sh.y), 0.f);
            v.z = fmaxf(fmaf(v.z, sc.z, sh.z), 0.f);
            v.w = fmaxf(fmaf(v.w, sc.w, sh.w), 0.f);
        }
        *(float4*)&As[r*LDA + c4*4] = v;
    }
    __syncthreads();

    const uint2* WH = (const uint2*)g_wfh;
    const uint2* WL = (const uint2*)g_wfl;

    #pragma unroll
    for (int k16 = 0; k16 < 8; k16++){
        // A fragments (2 m-tiles): bf16 hi/lo split from smem
        unsigned ah[2][4], al[2][4];
        #pragma unroll
        for (int mt=0; mt<2; mt++){
            int r0 = wm*32 + mt*16;
            #pragma unroll
            for (int q=0; q<4; q++){
                int rr = r0 + g + (q & 1)*8;
                int cc = k16*16 + 2*t + (q >> 1)*8;
                float2 f = *(const float2*)&As[rr*LDA + cc];
                unsigned h = pack_bf16(f.x, f.y);
                ah[mt][q] = h;
                al[mt][q] = pack_bf16(f.x - bf_lo(h), f.y - bf_hi(h));
            }
        }
        #pragma unroll
        for (int nt=0; nt<NTW; nt++){
            int off = (k16*NT + wn*NTW + nt)*32 + lane;
            uint2 bh = __ldg(&WH[off]);
            uint2 bl = __ldg(&WL[off]);
            unsigned bhv[2] = {bh.x, bh.y};
            unsigned blv[2] = {bl.x, bl.y};
            #pragma unroll
            for (int mt=0; mt<2; mt++){
                mma_bf16(acc[mt][nt], ah[mt], bhv);
                mma_bf16(acc[mt][nt], ah[mt], blv);
                mma_bf16(acc[mt][nt], al[mt], bhv);
            }
        }
    }

    // ---- store C -> g_bufB ----
    #pragma unroll
    for (int mt=0; mt<2; mt++){
        #pragma unroll
        for (int nt=0; nt<NTW; nt++){
            int col = (wn*NTW + nt)*8 + t*2;
            int r0  = rowBase + wm*32 + mt*16 + g;
            if (r0 < n)
                *(float2*)&g_bufB[(size_t)r0*DOUT + col] =
                    make_float2(acc[mt][nt][0], acc[mt][nt][1]);
            if (r0 + 8 < n)
                *(float2*)&g_bufB[(size_t)(r0+8)*DOUT + col] =
                    make_float2(acc[mt][nt][2], acc[mt][nt][3]);
        }
    }
}

// ---------------- aggregation + fused BN statistics (one warp-slot per node) -------
template<int D>
__global__ void __launch_bounds__(256) k_agg(int n){
    constexpr int F   = D/4;        // float4 per row (32 or 16)
    constexpr int NPW = 32/F;       // nodes per warp (1 or 2)
    __shared__ float ss[128], sq[128];
    int tid = threadIdx.x;
    if (tid < D){ ss[tid] = 0.f; sq[tid] = 0.f; }
    __syncthreads();

    int lane = tid & 31;
    int warp = (blockIdx.x*256 + tid) >> 5;
    int node = warp*NPW + lane/F;
    int fi   = lane % F;

    const float4* t = (const float4*)g_bufB;
    float4* o = (float4*)g_bufA;

    if (node < n){
        float idg = g_invdeg[node];
        float4 v = t[(size_t)node*F + fi];
        float4 acc = make_float4(v.x*idg, v.y*idg, v.z*idg, v.w*idg);

        int p0 = g_rowptr[node], p1 = g_rowptr[node+1];
        int p = p0;
        for (; p + 1 < p1; p += 2){
            int   s0 = g_cols[p],   s1 = g_cols[p+1];
            float w0 = g_vals[p],   w1 = g_vals[p+1];
            float4 u0 = t[(size_t)s0*F + fi];
            float4 u1 = t[(size_t)s1*F + fi];
            acc.x = fmaf(w0,u0.x, fmaf(w1,u1.x, acc.x));
            acc.y = fmaf(w0,u0.y, fmaf(w1,u1.y, acc.y));
            acc.z = fmaf(w0,u0.z, fmaf(w1,u1.z, acc.z));
            acc.w = fmaf(w0,u0.w, fmaf(w1,u1.w, acc.w));
        }
        if (p < p1){
            int   s0 = g_cols[p];
            float w0 = g_vals[p];
            float4 u0 = t[(size_t)s0*F + fi];
            acc.x = fmaf(w0,u0.x, acc.x);
            acc.y = fmaf(w0,u0.y, acc.y);
            acc.z = fmaf(w0,u0.z, acc.z);
            acc.w = fmaf(w0,u0.w, acc.w);
        }
        o[(size_t)node*F + fi] = acc;

        int ch = fi*4;
        atomicAdd(&ss[ch+0], acc.x); atomicAdd(&sq[ch+0], acc.x*acc.x);
        atomicAdd(&ss[ch+1], acc.y); atomicAdd(&sq[ch+1], acc.y*acc.y);
        atomicAdd(&ss[ch+2], acc.z); atomicAdd(&sq[ch+2], acc.z*acc.z);
        atomicAdd(&ss[ch+3], acc.w); atomicAdd(&sq[ch+3], acc.w*acc.w);
    }
    __syncthreads();
    if (tid < D){
        atomicAdd(&g_stats[tid],       ss[tid]);
        atomicAdd(&g_stats[128 + tid], sq[tid]);
    }
}

// ---------------- batch-norm finalize ----------------
__global__ void k_bn_final(const float* __restrict__ g, const float* __restrict__ be,
                           int n, int D){
    int c = threadIdx.x;                 // 256 threads
    float sc = 0.f, sh = 0.f;
    if (c < D){
        float inv_n = 1.0f / (float)n;
        float mu  = g_stats[c] * inv_n;
        float var = g_stats[128 + c] * inv_n - mu*mu;
        sc = g[c] * rsqrtf(var + 1e-5f);
        sh = be[c] - mu*sc;
    }
    __syncthreads();
    g_stats[c] = 0.f;
    if (c < D){ g_scale[c] = sc; g_shift[c] = sh; }
}

// ---------------- head ----------------
__global__ void __launch_bounds__(256) k_head(const float* __restrict__ wc1,
                                              const float* __restrict__ bc1,
                                              const float* __restrict__ wc2,
                                              const float* __restrict__ bc2,
                                              float* __restrict__ out, int n){
    __shared__ float w1s[64*32];
    __shared__ float b1s[32], w2s[32], scs[64], shs[64];
    int tid = threadIdx.x;
    for (int i = tid; i < 64*32; i += 256) w1s[i] = wc1[i];
    if (tid < 32){ b1s[tid] = bc1[tid]; w2s[tid] = wc2[tid]; }
    if (tid < 64){ scs[tid] = g_scale[tid]; shs[tid] = g_shift[tid]; }
    __syncthreads();

    int warp = (blockIdx.x*256 + tid) >> 5;
    int lane = tid & 31;
    if (warp >= n) return;

    const float* row = &g_bufA[(size_t)warp * 64];
    float a0 = b1s[lane], a1 = 0.f, a2 = 0.f, a3 = 0.f;
    #pragma unroll
    for (int k = 0; k < 64; k += 4){
        float v0 = fmaxf(fmaf(row[k+0], scs[k+0], shs[k+0]), 0.f);
        float v1 = fmaxf(fmaf(row[k+1], scs[k+1], shs[k+1]), 0.f);
        float v2 = fmaxf(fmaf(row[k+2], scs[k+2], shs[k+2]), 0.f);
        float v3 = fmaxf(fmaf(row[k+3], scs[k+3], shs[k+3]), 0.f);
        a0 = fmaf(v0, w1s[(k+0)*32 + lane], a0);
        a1 = fmaf(v1, w1s[(k+1)*32 + lane], a1);
        a2 = fmaf(v2, w1s[(k+2)*32 + lane], a2);
        a3 = fmaf(v3, w1s[(k+3)*32 + lane], a3);
    }
    float h = fmaxf((a0+a1)+(a2+a3), 0.f) * w2s[lane];
    #pragma unroll
    for (int off = 16; off; off >>= 1) h += __shfl_xor_sync(0xffffffff, h, off);
    if (lane == 0) out[warp] = h + bc2[0];
}

// ---------------- launch ----------------
extern "C" void kernel_launch(void* const* d_in, const int* in_sizes, int n_in,
                              void* d_out, int out_size){
    const float* x   = (const float*)d_in[0];
    const void*  ei  = d_in[1];
    const float* w0  = (const float*)d_in[2];
    const float* g0  = (const float*)d_in[4];
    const float* be0 = (const float*)d_in[5];
    const float* w1  = (const float*)d_in[6];
    const float* g1  = (const float*)d_in[8];
    const float* be1 = (const float*)d_in[9];
    const float* w2  = (const float*)d_in[10];
    const float* g2  = (const float*)d_in[12];
    const float* be2 = (const float*)d_in[13];
    const float* wc1 = (const float*)d_in[14];
    const float* bc1 = (const float*)d_in[15];
    const float* wc2 = (const float*)d_in[16];
    const float* bc2 = (const float*)d_in[17];
    float* out = (float*)d_out;

    int n = in_sizes[0] / 128;
    int E = in_sizes[1] / 2;

    const int GSMEM = 128*136*4;     // 69632 B dynamic smem for GEMM
    cudaFuncSetAttribute(k_gemm_bf<128,0>, cudaFuncAttributeMaxDynamicSharedMemorySize, GSMEM);
    cudaFuncSetAttribute(k_gemm_bf<128,1>, cudaFuncAttributeMaxDynamicSharedMemorySize, GSMEM);
    cudaFuncSetAttribute(k_gemm_bf<64,1>,  cudaFuncAttributeMaxDynamicSharedMemorySize, GSMEM);

    int gemmGrid = CDIV(n, 128);

    // my launch #4 = layer-0 GEMM (harness launches 2 kernels first; ncu -s 5 -c 1)
    k_detect<<<1,1>>>(ei);                                       // 1
    k_zero_cnt<<<CDIV(n,256),256>>>(n);                          // 2
    k_wsplit<128><<<CDIV(64*128,256),256>>>(w0);                 // 3
    k_gemm_bf<128,0><<<gemmGrid,256,GSMEM>>>(x, n);              // 4 <- profiled
    k_hist<<<CDIV(E,256),256>>>(ei, E);                          // 5
    k_deg<<<CDIV(n,256),256>>>(n);                               // 6
    k_scan<<<1,1024>>>(n);                                       // 7 (also zeroes stats)
    k_zero_cnt<<<CDIV(n,256),256>>>(n);                          // 8
    k_fill<<<CDIV(E,256),256>>>(ei, E);                          // 9

    // ---- layer 0 (128 -> 128) ----
    k_agg<128><<<CDIV(n*32,256),256>>>(n);                       // 10
    k_bn_final<<<1,256>>>(g0, be0, n, 128);                      // 11

    // ---- layer 1 (128 -> 128) ----
    k_wsplit<128><<<CDIV(64*128,256),256>>>(w1);                 // 12
    k_gemm_bf<128,1><<<gemmGrid,256,GSMEM>>>(nullptr, n);        // 13
    k_agg<128><<<CDIV(n*32,256),256>>>(n);                       // 14
    k_bn_final<<<1,256>>>(g1, be1, n, 128);                      // 15

    // ---- layer 2 (128 -> 64) ----
    k_wsplit<64><<<CDIV(64*64,256),256>>>(w2);                   // 16
    k_gemm_bf<64,1><<<gemmGrid,256,GSMEM>>>(nullptr, n);         // 17
    k_agg<64><<<CDIV(n*16,256),256>>>(n);                        // 18
    k_bn_final<<<1,256>>>(g2, be2, n, 64);                       // 19

    // ---- head ----
    k_head<<<CDIV(n*32,256),256>>>(wc1, bc1, wc2, bc2, out, n);  // 20
}